// round 13
// baseline (speedup 1.0000x reference)
#include <cuda_runtime.h>
#include <math_constants.h>

#define N_NODES 50000
#define N_EDGES 1600000
#define HEADS 8
#define OUT_FEAT 16
#define IN_FEAT 128
#define HF 128            // HEADS*OUT_FEAT
#define CAP 128           // per-node slot capacity (Poisson(32); P(>128) ~ 1e-35)
#define TILE_N 32         // nodes per k_proj block (1 per thread)
#define KC 64             // k-chunk size (2 chunks)

// ---- scratch (device globals; no allocations allowed) ----
__device__ float4 g_h4[N_NODES * 32];      // h as float4 [N][H][4] = 25.6 MB
__device__ float4 g_post[N_NODES * HEADS]; // (loc_l, loc_r, exp(lsl), exp(lsr)), 6.4 MB
__device__ int2   g_es[(size_t)N_NODES * CAP]; // bucket: {src, edge_id}
__device__ int    g_cur[N_NODES];          // per-node slot cursor (zeroed at load; reset by k_node)

#define FMA2(acc, a, b) \
    asm("fma.rn.f32x2 %0, %1, %2, %0;" : "+l"(acc) : "l"(a), "l"(b))

// ---- projection: h = feat @ W_fc ; post = h @ W_post + b_post ----
// 32 nodes/block, 1 node/thread, warp = head. KC=64 (2 chunks, 4 barriers).
// 40.4 KB smem -> 5 blocks/SM (40 warps). per kk: 1 LDS.32 + 4 LDS.128 bcast
// + 8 FFMA2 for 32 MACs.
__global__ void __launch_bounds__(256, 5)
k_proj(const float* __restrict__ feat, const float* __restrict__ W_fc,
       const float* __restrict__ W_post, const float* __restrict__ b_post) {
    __shared__ float sfT[KC][TILE_N + 1];   // transposed feat chunk, 8.45 KB
    __shared__ float sw[KC][HF];            // weight K-chunk, 32 KB
    int t = threadIdx.x;
    int lane = t & 31;
    int hd = t >> 5;                        // warp id == head
    int n0 = blockIdx.x * TILE_N;
    int c0 = hd * 16;

    unsigned long long acc2[8];
#pragma unroll
    for (int j = 0; j < 8; ++j) acc2[j] = 0ULL;

    for (int kc = 0; kc < IN_FEAT; kc += KC) {
        __syncthreads();
        // W chunk: 64x128 floats = 2048 float4, 8 per thread (coalesced)
#pragma unroll
        for (int i = t; i < KC * HF / 4; i += 256) {
            int row = i >> 5, c4 = i & 31;
            float4 v = ((const float4*)(W_fc + (size_t)(kc + row) * HF))[c4];
            *(float4*)&sw[row][c4 * 4] = v;
        }
        // feat chunk: 32 nodes x 64 = 512 float4, 2 per thread; transpose-store
#pragma unroll
        for (int i = t; i < TILE_N * KC / 4; i += 256) {
            int r = i >> 4, c4 = i & 15;
            int n = n0 + r;
            float4 v = (n < N_NODES)
                ? ((const float4*)(feat + (size_t)n * IN_FEAT + kc))[c4]
                : make_float4(0.f, 0.f, 0.f, 0.f);
            sfT[c4 * 4 + 0][r] = v.x;
            sfT[c4 * 4 + 1][r] = v.y;
            sfT[c4 * 4 + 2][r] = v.z;
            sfT[c4 * 4 + 3][r] = v.w;
        }
        __syncthreads();
#pragma unroll 8
        for (int kk = 0; kk < KC; ++kk) {
            float a = sfT[kk][lane];
            unsigned long long av;
            asm("mov.b64 %0, {%1, %1};" : "=l"(av) : "f"(a));
            const ulonglong2* swp = (const ulonglong2*)&sw[kk][c0];
            ulonglong2 q0 = swp[0], q1 = swp[1], q2 = swp[2], q3 = swp[3]; // LDS.128 bcast
            FMA2(acc2[0], av, q0.x); FMA2(acc2[1], av, q0.y);
            FMA2(acc2[2], av, q1.x); FMA2(acc2[3], av, q1.y);
            FMA2(acc2[4], av, q2.x); FMA2(acc2[5], av, q2.y);
            FMA2(acc2[6], av, q3.x); FMA2(acc2[7], av, q3.y);
        }
    }

    int n = n0 + lane;
    if (n < N_NODES) {
        float acc[16];
#pragma unroll
        for (int j = 0; j < 8; ++j)
            asm("mov.b64 {%0, %1}, %2;" : "=f"(acc[2 * j]), "=f"(acc[2 * j + 1]) : "l"(acc2[j]));
#pragma unroll
        for (int q = 0; q < 4; ++q)
            g_h4[n * 32 + hd * 4 + q] =
                make_float4(acc[4 * q], acc[4 * q + 1], acc[4 * q + 2], acc[4 * q + 3]);
        float p0 = b_post[0], p1 = b_post[1], p2 = b_post[2], p3 = b_post[3];
#pragma unroll
        for (int j = 0; j < 16; ++j) {
            float hv = acc[j];
            p0 = fmaf(hv, W_post[j * 4 + 0], p0);
            p1 = fmaf(hv, W_post[j * 4 + 1], p1);
            p2 = fmaf(hv, W_post[j * 4 + 2], p2);
            p3 = fmaf(hv, W_post[j * 4 + 3], p3);
        }
        g_post[n * HEADS + hd] = make_float4(p0, p1, __expf(p2), __expf(p3));
    }
}

// ---- per-edge: slot assignment only ----
__global__ void k_edge(const int* __restrict__ src, const int* __restrict__ dst) {
    int e = blockIdx.x * blockDim.x + threadIdx.x;
    if (e >= N_EDGES) return;
    int d = dst[e];
    int c = atomicAdd(&g_cur[d], 1);
    if (c < CAP) g_es[(size_t)d * CAP + c] = make_int2(src[e], e);
}

// ---- per-node: WARP PAIR per node (64 threads) ----
__global__ void k_node(const float* __restrict__ eps,
                       const float* __restrict__ bias, float* __restrict__ out) {
    __shared__ float ssc[4][CAP * 8];   // per-pair exp-scores, 16 KB
    __shared__ int   ssn[4][CAP];       // per-pair src ids, 2 KB
    __shared__ float sdn[4][16];        // per-pair partial denoms
    int wl = threadIdx.x >> 5;
    int p  = wl >> 1;
    int wp = wl & 1;
    int nd = blockIdx.x * 4 + p;        // exact: 12500 * 4 = 50000
    int lane = threadIdx.x & 31;
    int cnt = min(g_cur[nd], CAP);
    const unsigned full = 0xFFFFFFFFu;
    const int2* bkt = g_es + (size_t)nd * CAP;
    float* sc = ssc[p];
    int*   sn = ssn[p];

    // ---- phase A: x = exp(score) for all 8 heads, pair-cooperative ----
    int head = lane & 7;
    int sgrp = (wp * 32 + lane) >> 3;
    float4 pd = g_post[nd * HEADS + head];
    float ds = 0.0f;
    for (int s = sgrp; s < cnt; s += 8) {
        int2 se = bkt[s];
        float4 ps = g_post[se.x * HEADS + head];
        float ep  = eps[(size_t)se.y * HEADS + head];
        float x = __expf(fmaf(ps.z * pd.w, ep, ps.x + pd.y));
        sc[s * 8 + head] = x;
        if (head == 0) sn[s] = se.x;
        ds += x;
    }
    ds += __shfl_xor_sync(full, ds, 8);
    ds += __shfl_xor_sync(full, ds, 16);
    if (lane < 8) sdn[p][wp * 8 + lane] = ds;
    __syncthreads();
    if (wp == 0 && lane == 0) g_cur[nd] = 0;   // reset cursor for next replay

    // ---- phase B: weighted aggregation, warp = (node, half) ----
    int hd4 = lane >> 3;
    int head_b = wp * 4 + hd4;
    float dtot = sdn[p][head_b] + sdn[p][8 + head_b];
    const float2* h2 = (const float2*)g_h4;
    int base2 = wp * 32 + lane;
    const float2* bias2 = (const float2*)bias;
    float2 bv = bias2[base2];
    float2 acc = make_float2(0.f, 0.f);

    int s = 0;
    for (; s + 2 <= cnt; s += 2) {
        int sn0 = sn[s], sn1 = sn[s + 1];
        float x0 = sc[(s    ) * 8 + head_b];
        float x1 = sc[(s + 1) * 8 + head_b];
        float2 v0 = h2[(size_t)sn0 * 64 + base2];
        float2 v1 = h2[(size_t)sn1 * 64 + base2];
        acc.x = fmaf(v0.x, x0, acc.x); acc.y = fmaf(v0.y, x0, acc.y);
        acc.x = fmaf(v1.x, x1, acc.x); acc.y = fmaf(v1.y, x1, acc.y);
    }
    if (s < cnt) {
        int sn0 = sn[s];
        float x0 = sc[s * 8 + head_b];
        float2 v0 = h2[(size_t)sn0 * 64 + base2];
        acc.x = fmaf(v0.x, x0, acc.x); acc.y = fmaf(v0.y, x0, acc.y);
    }
    if (cnt > 0) {
        float rd = 1.0f / dtot;
        acc.x *= rd; acc.y *= rd;
    }
    acc.x += bv.x; acc.y += bv.y;
    ((float2*)out)[(size_t)nd * 64 + base2] = acc;
}

extern "C" void kernel_launch(void* const* d_in, const int* in_sizes, int n_in,
                              void* d_out, int out_size) {
    const float* feat   = (const float*)d_in[0];
    const int*   src    = (const int*)  d_in[1];
    const int*   dst    = (const int*)  d_in[2];
    const float* eps    = (const float*)d_in[3];
    const float* W_fc   = (const float*)d_in[4];
    const float* W_post = (const float*)d_in[5];
    const float* b_post = (const float*)d_in[6];
    const float* bias   = (const float*)d_in[7];
    float* out = (float*)d_out;

    k_proj <<<(N_NODES + TILE_N - 1) / TILE_N, 256>>>(feat, W_fc, W_post, b_post);
    k_edge <<<(N_EDGES + 255) / 256, 256>>>(src, dst);
    k_node <<<N_NODES / 4, 256>>>(eps, bias, out);   // 12500 blocks exact
}

// round 14
// speedup vs baseline: 1.2899x; 1.2899x over previous
#include <cuda_runtime.h>
#include <math_constants.h>

#define N_NODES 50000
#define N_EDGES 1600000
#define HEADS 8
#define OUT_FEAT 16
#define IN_FEAT 128
#define HF 128            // HEADS*OUT_FEAT
#define CAP 128           // per-node slot capacity (Poisson(32); P(>128) ~ 1e-35)
#define TILE_N 64         // nodes per k_proj block (2 per thread)

// ---- scratch (device globals; no allocations allowed) ----
__device__ float4 g_h4[N_NODES * 32];      // h as float4 [N][H][4] = 25.6 MB
__device__ float4 g_post[N_NODES * HEADS]; // (loc_l, loc_r, exp(lsl), exp(lsr)), 6.4 MB
__device__ int2   g_es[(size_t)N_NODES * CAP]; // bucket: {src, edge_id}
__device__ int    g_cur[N_NODES];          // per-node slot cursor (zeroed at load; reset by k_node)

#define FMA2(acc, a, b) \
    asm("fma.rn.f32x2 %0, %1, %2, %0;" : "+l"(acc) : "l"(a), "l"(b))

// ---- projection: h = feat @ W_fc ; post = h @ W_post + b_post ----
// 64 nodes/block, 2 nodes/thread, warp = head. NO weight smem: W_fc (64 KB)
// is read via broadcast LDG.128 and stays L1-resident (all warps share it).
// One barrier total; 128-deep unfenced FFMA2 loop.
__global__ void __launch_bounds__(256, 4)
k_proj(const float* __restrict__ feat, const float* __restrict__ W_fc,
       const float* __restrict__ W_post, const float* __restrict__ b_post) {
    __shared__ float sfT[IN_FEAT][TILE_N + 1];  // transposed feat tile, 33.3 KB
    int t = threadIdx.x;
    int lane = t & 31;
    int hd = t >> 5;                    // warp id == head
    int n0 = blockIdx.x * TILE_N;
    int c0 = hd * 16;

    // one-time feat tile load (coalesced rows, transposed store, padded)
    for (int i = t; i < TILE_N * IN_FEAT; i += 256) {
        int r = i >> 7, c = i & 127;
        int n = n0 + r;
        sfT[c][r] = (n < N_NODES) ? feat[(size_t)n * IN_FEAT + c] : 0.0f;
    }
    __syncthreads();

    unsigned long long accA2[8], accB2[8];
#pragma unroll
    for (int j = 0; j < 8; ++j) { accA2[j] = 0ULL; accB2[j] = 0ULL; }

#pragma unroll 8
    for (int kk = 0; kk < IN_FEAT; ++kk) {
        float a0 = sfT[kk][lane];
        float a1 = sfT[kk][lane + 32];
        unsigned long long av0, av1;
        asm("mov.b64 %0, {%1, %1};" : "=l"(av0) : "f"(a0));
        asm("mov.b64 %0, {%1, %1};" : "=l"(av1) : "f"(a1));
        const ulonglong2* wp = (const ulonglong2*)(W_fc + (size_t)kk * HF + c0);
        ulonglong2 q0 = wp[0], q1 = wp[1], q2 = wp[2], q3 = wp[3]; // LDG.128 bcast, L1-hot
        FMA2(accA2[0], av0, q0.x); FMA2(accB2[0], av1, q0.x);
        FMA2(accA2[1], av0, q0.y); FMA2(accB2[1], av1, q0.y);
        FMA2(accA2[2], av0, q1.x); FMA2(accB2[2], av1, q1.x);
        FMA2(accA2[3], av0, q1.y); FMA2(accB2[3], av1, q1.y);
        FMA2(accA2[4], av0, q2.x); FMA2(accB2[4], av1, q2.x);
        FMA2(accA2[5], av0, q2.y); FMA2(accB2[5], av1, q2.y);
        FMA2(accA2[6], av0, q3.x); FMA2(accB2[6], av1, q3.x);
        FMA2(accA2[7], av0, q3.y); FMA2(accB2[7], av1, q3.y);
    }

#pragma unroll
    for (int half = 0; half < 2; ++half) {
        int n = n0 + lane + half * 32;
        unsigned long long* acc2 = half ? accB2 : accA2;
        if (n < N_NODES) {
            float acc[16];
#pragma unroll
            for (int j = 0; j < 8; ++j)
                asm("mov.b64 {%0, %1}, %2;" : "=f"(acc[2 * j]), "=f"(acc[2 * j + 1]) : "l"(acc2[j]));
#pragma unroll
            for (int q = 0; q < 4; ++q)
                g_h4[n * 32 + hd * 4 + q] =
                    make_float4(acc[4 * q], acc[4 * q + 1], acc[4 * q + 2], acc[4 * q + 3]);
            float p0 = b_post[0], p1 = b_post[1], p2 = b_post[2], p3 = b_post[3];
#pragma unroll
            for (int j = 0; j < 16; ++j) {
                float hv = acc[j];
                p0 = fmaf(hv, W_post[j * 4 + 0], p0);
                p1 = fmaf(hv, W_post[j * 4 + 1], p1);
                p2 = fmaf(hv, W_post[j * 4 + 2], p2);
                p3 = fmaf(hv, W_post[j * 4 + 3], p3);
            }
            g_post[n * HEADS + hd] = make_float4(p0, p1, __expf(p2), __expf(p3));
        }
    }
}

// ---- per-edge: slot assignment only ----
__global__ void k_edge(const int* __restrict__ src, const int* __restrict__ dst) {
    int e = blockIdx.x * blockDim.x + threadIdx.x;
    if (e >= N_EDGES) return;
    int d = dst[e];
    int c = atomicAdd(&g_cur[d], 1);
    if (c < CAP) g_es[(size_t)d * CAP + c] = make_int2(src[e], e);
}

// ---- per-node: WARP PAIR per node (64 threads) ----
__global__ void k_node(const float* __restrict__ eps,
                       const float* __restrict__ bias, float* __restrict__ out) {
    __shared__ float ssc[4][CAP * 8];   // per-pair exp-scores, 16 KB
    __shared__ int   ssn[4][CAP];       // per-pair src ids, 2 KB
    __shared__ float sdn[4][16];        // per-pair partial denoms
    int wl = threadIdx.x >> 5;
    int p  = wl >> 1;
    int wp = wl & 1;
    int nd = blockIdx.x * 4 + p;        // exact: 12500 * 4 = 50000
    int lane = threadIdx.x & 31;
    int cnt = min(g_cur[nd], CAP);
    const unsigned full = 0xFFFFFFFFu;
    const int2* bkt = g_es + (size_t)nd * CAP;
    float* sc = ssc[p];
    int*   sn = ssn[p];

    // ---- phase A: x = exp(score) for all 8 heads, pair-cooperative ----
    int head = lane & 7;
    int sgrp = (wp * 32 + lane) >> 3;
    float4 pd = g_post[nd * HEADS + head];
    float ds = 0.0f;
    for (int s = sgrp; s < cnt; s += 8) {
        int2 se = bkt[s];
        float4 ps = g_post[se.x * HEADS + head];
        float ep  = eps[(size_t)se.y * HEADS + head];
        float x = __expf(fmaf(ps.z * pd.w, ep, ps.x + pd.y));
        sc[s * 8 + head] = x;
        if (head == 0) sn[s] = se.x;
        ds += x;
    }
    ds += __shfl_xor_sync(full, ds, 8);
    ds += __shfl_xor_sync(full, ds, 16);
    if (lane < 8) sdn[p][wp * 8 + lane] = ds;
    __syncthreads();
    if (wp == 0 && lane == 0) g_cur[nd] = 0;   // reset cursor for next replay

    // ---- phase B: weighted aggregation, warp = (node, half) ----
    int hd4 = lane >> 3;
    int head_b = wp * 4 + hd4;
    float dtot = sdn[p][head_b] + sdn[p][8 + head_b];
    const float2* h2 = (const float2*)g_h4;
    int base2 = wp * 32 + lane;
    const float2* bias2 = (const float2*)bias;
    float2 bv = bias2[base2];
    float2 acc = make_float2(0.f, 0.f);

    int s = 0;
    for (; s + 2 <= cnt; s += 2) {
        int sn0 = sn[s], sn1 = sn[s + 1];
        float x0 = sc[(s    ) * 8 + head_b];
        float x1 = sc[(s + 1) * 8 + head_b];
        float2 v0 = h2[(size_t)sn0 * 64 + base2];
        float2 v1 = h2[(size_t)sn1 * 64 + base2];
        acc.x = fmaf(v0.x, x0, acc.x); acc.y = fmaf(v0.y, x0, acc.y);
        acc.x = fmaf(v1.x, x1, acc.x); acc.y = fmaf(v1.y, x1, acc.y);
    }
    if (s < cnt) {
        int sn0 = sn[s];
        float x0 = sc[s * 8 + head_b];
        float2 v0 = h2[(size_t)sn0 * 64 + base2];
        acc.x = fmaf(v0.x, x0, acc.x); acc.y = fmaf(v0.y, x0, acc.y);
    }
    if (cnt > 0) {
        float rd = 1.0f / dtot;
        acc.x *= rd; acc.y *= rd;
    }
    acc.x += bv.x; acc.y += bv.y;
    ((float2*)out)[(size_t)nd * 64 + base2] = acc;
}

extern "C" void kernel_launch(void* const* d_in, const int* in_sizes, int n_in,
                              void* d_out, int out_size) {
    const float* feat   = (const float*)d_in[0];
    const int*   src    = (const int*)  d_in[1];
    const int*   dst    = (const int*)  d_in[2];
    const float* eps    = (const float*)d_in[3];
    const float* W_fc   = (const float*)d_in[4];
    const float* W_post = (const float*)d_in[5];
    const float* b_post = (const float*)d_in[6];
    const float* bias   = (const float*)d_in[7];
    float* out = (float*)d_out;

    k_proj <<<(N_NODES + TILE_N - 1) / TILE_N, 256>>>(feat, W_fc, W_post, b_post);
    k_edge <<<(N_EDGES + 255) / 256, 256>>>(src, dst);
    k_node <<<N_NODES / 4, 256>>>(eps, bias, out);   // 12500 blocks exact
}

// round 15
// speedup vs baseline: 1.5281x; 1.1847x over previous
#include <cuda_runtime.h>
#include <math_constants.h>

#define N_NODES 50000
#define N_EDGES 1600000
#define HEADS 8
#define OUT_FEAT 16
#define IN_FEAT 128
#define HF 128            // HEADS*OUT_FEAT
#define CAP 128           // per-node slot capacity (Poisson(32); P(>128) ~ 1e-35)
#define TILE_N 64         // nodes per k_proj block (2 per thread)

// ---- scratch (device globals; no allocations allowed) ----
__device__ float4 g_h4[N_NODES * 32];      // h as float4 [N][H][4] = 25.6 MB
__device__ float4 g_post[N_NODES * HEADS]; // (loc_l, loc_r, exp(lsl), exp(lsr)), 6.4 MB
__device__ int2   g_es[(size_t)N_NODES * CAP]; // bucket: {src, edge_id}
__device__ int    g_cur[N_NODES];          // per-node slot cursor (zeroed at load; reset by k_node)

#define FMA2(acc, a, b) \
    asm("fma.rn.f32x2 %0, %1, %2, %0;" : "+l"(acc) : "l"(a), "l"(b))

// ---- projection (EXACT R10 version, measured 66.5us): h = feat@W_fc; post ----
__global__ void k_proj(const float* __restrict__ feat, const float* __restrict__ W_fc,
                       const float* __restrict__ W_post, const float* __restrict__ b_post) {
    __shared__ float sfT[IN_FEAT][TILE_N + 1];  // transposed feat tile
    __shared__ float sw[32][HF];                // weight K-chunk
    int t = threadIdx.x;
    int lane = t & 31;
    int hd = t >> 5;                            // warp id == head
    int n0 = blockIdx.x * TILE_N;
    int c0 = hd * 16;

    for (int i = t; i < TILE_N * IN_FEAT; i += 256) {
        int r = i >> 7, c = i & 127;
        int n = n0 + r;
        sfT[c][r] = (n < N_NODES) ? feat[(size_t)n * IN_FEAT + c] : 0.0f;
    }

    unsigned long long accA2[8], accB2[8];
#pragma unroll
    for (int j = 0; j < 8; ++j) { accA2[j] = 0ULL; accB2[j] = 0ULL; }

    for (int kc = 0; kc < IN_FEAT; kc += 32) {
        __syncthreads();
        for (int i = t; i < 32 * HF; i += 256) {
            int kk = i >> 7, c = i & 127;
            sw[kk][c] = W_fc[(size_t)(kc + kk) * HF + c];
        }
        __syncthreads();
#pragma unroll 4
        for (int kk = 0; kk < 32; ++kk) {
            float a0 = sfT[kc + kk][lane];
            float a1 = sfT[kc + kk][lane + 32];
            unsigned long long av0, av1;
            asm("mov.b64 %0, {%1, %1};" : "=l"(av0) : "f"(a0));
            asm("mov.b64 %0, {%1, %1};" : "=l"(av1) : "f"(a1));
            const unsigned long long* swp = (const unsigned long long*)&sw[kk][c0];
#pragma unroll
            for (int j = 0; j < 8; ++j) {
                unsigned long long bj = swp[j];      // broadcast LDS.64
                FMA2(accA2[j], av0, bj);
                FMA2(accB2[j], av1, bj);
            }
        }
    }

#pragma unroll
    for (int half = 0; half < 2; ++half) {
        int n = n0 + lane + half * 32;
        unsigned long long* acc2 = half ? accB2 : accA2;
        if (n < N_NODES) {
            float acc[16];
#pragma unroll
            for (int j = 0; j < 8; ++j)
                asm("mov.b64 {%0, %1}, %2;" : "=f"(acc[2 * j]), "=f"(acc[2 * j + 1]) : "l"(acc2[j]));
#pragma unroll
            for (int q = 0; q < 4; ++q)
                g_h4[n * 32 + hd * 4 + q] =
                    make_float4(acc[4 * q], acc[4 * q + 1], acc[4 * q + 2], acc[4 * q + 3]);
            float p0 = b_post[0], p1 = b_post[1], p2 = b_post[2], p3 = b_post[3];
#pragma unroll
            for (int j = 0; j < 16; ++j) {
                float hv = acc[j];
                p0 = fmaf(hv, W_post[j * 4 + 0], p0);
                p1 = fmaf(hv, W_post[j * 4 + 1], p1);
                p2 = fmaf(hv, W_post[j * 4 + 2], p2);
                p3 = fmaf(hv, W_post[j * 4 + 3], p3);
            }
            g_post[n * HEADS + hd] = make_float4(p0, p1, __expf(p2), __expf(p3));
        }
    }
}

// ---- per-edge: slot assignment only ----
__global__ void k_edge(const int* __restrict__ src, const int* __restrict__ dst) {
    int e = blockIdx.x * blockDim.x + threadIdx.x;
    if (e >= N_EDGES) return;
    int d = dst[e];
    int c = atomicAdd(&g_cur[d], 1);
    if (c < CAP) g_es[(size_t)d * CAP + c] = make_int2(src[e], e);
}

// ---- per-node: WARP PAIR per node; phase B = 2 edges per warp iteration ----
// phase B layout: lane = half16*16 + l16. half16 selects edge s/s+1; l16 is the
// float4 output chunk. One LDG.128 per lane per 2 edges; halves combined by shfl.
__global__ void k_node(const float* __restrict__ eps,
                       const float* __restrict__ bias, float* __restrict__ out) {
    __shared__ float ssc[4][(CAP + 1) * 8];  // per-pair exp-scores (+pad slot)
    __shared__ int   ssn[4][CAP + 1];        // per-pair src ids (+pad slot)
    __shared__ float sdn[4][16];             // per-pair partial denoms
    int wl = threadIdx.x >> 5;
    int p  = wl >> 1;
    int wp = wl & 1;
    int nd = blockIdx.x * 4 + p;        // exact: 12500 * 4 = 50000
    int lane = threadIdx.x & 31;
    int cnt = min(g_cur[nd], CAP);
    const unsigned full = 0xFFFFFFFFu;
    const int2* bkt = g_es + (size_t)nd * CAP;
    float* sc = ssc[p];
    int*   sn = ssn[p];

    // ---- phase A: x = exp(score) for all 8 heads, pair-cooperative ----
    int head = lane & 7;
    int sgrp = (wp * 32 + lane) >> 3;
    float4 pd = g_post[nd * HEADS + head];
    float ds = 0.0f;
    for (int s = sgrp; s < cnt; s += 8) {
        int2 se = bkt[s];
        float4 ps = g_post[se.x * HEADS + head];
        float ep  = eps[(size_t)se.y * HEADS + head];
        float x = __expf(fmaf(ps.z * pd.w, ep, ps.x + pd.y));
        sc[s * 8 + head] = x;
        if (head == 0) sn[s] = se.x;
        ds += x;
    }
    ds += __shfl_xor_sync(full, ds, 8);
    ds += __shfl_xor_sync(full, ds, 16);
    if (lane < 8) sdn[p][wp * 8 + lane] = ds;
    // zero-pad slot cnt (covers odd-cnt tail; x=0 contributes nothing)
    if (wp == 0 && lane < 8 && cnt < CAP) sc[cnt * 8 + lane] = 0.0f;
    if (wp == 0 && lane == 8 && cnt < CAP) sn[cnt] = 0;
    __syncthreads();
    if (wp == 0 && lane == 0) g_cur[nd] = 0;   // reset cursor for next replay

    // ---- phase B: 2 edges per iteration, float4 chunks ----
    int half16 = lane >> 4;            // which edge of the pair
    int l16    = lane & 15;            // float4 chunk within warp's 64 floats
    int head_b = wp * 4 + (l16 >> 2);  // head of this chunk
    int chunk  = wp * 16 + l16;        // float4 index within node's 32
    float4 acc = make_float4(0.f, 0.f, 0.f, 0.f);

#pragma unroll 2
    for (int s = 0; s < cnt; s += 2) {
        int   snv = sn[s + half16];                    // 1 LDS, 2 bcast groups
        float x   = sc[(s + half16) * 8 + head_b];     // 1 LDS, 8 bcast groups
        float4 v  = g_h4[(size_t)snv * 32 + chunk];    // LDG.128, 256B/node
        acc.x = fmaf(v.x, x, acc.x); acc.y = fmaf(v.y, x, acc.y);
        acc.z = fmaf(v.z, x, acc.z); acc.w = fmaf(v.w, x, acc.w);
    }
    // combine the two edge-halves
    acc.x += __shfl_xor_sync(full, acc.x, 16);
    acc.y += __shfl_xor_sync(full, acc.y, 16);
    acc.z += __shfl_xor_sync(full, acc.z, 16);
    acc.w += __shfl_xor_sync(full, acc.w, 16);

    if (half16 == 0) {
        float dtot = sdn[p][head_b] + sdn[p][8 + head_b];
        float rd = (cnt > 0) ? 1.0f / dtot : 0.0f;
        float4 bv = ((const float4*)bias)[chunk];
        float4 o;
        o.x = fmaf(acc.x, rd, bv.x);
        o.y = fmaf(acc.y, rd, bv.y);
        o.z = fmaf(acc.z, rd, bv.z);
        o.w = fmaf(acc.w, rd, bv.w);
        ((float4*)out)[(size_t)nd * 32 + chunk] = o;
    }
}

extern "C" void kernel_launch(void* const* d_in, const int* in_sizes, int n_in,
                              void* d_out, int out_size) {
    const float* feat   = (const float*)d_in[0];
    const int*   src    = (const int*)  d_in[1];
    const int*   dst    = (const int*)  d_in[2];
    const float* eps    = (const float*)d_in[3];
    const float* W_fc   = (const float*)d_in[4];
    const float* W_post = (const float*)d_in[5];
    const float* b_post = (const float*)d_in[6];
    const float* bias   = (const float*)d_in[7];
    float* out = (float*)d_out;

    k_proj <<<(N_NODES + TILE_N - 1) / TILE_N, 256>>>(feat, W_fc, W_post, b_post);
    k_edge <<<(N_EDGES + 255) / 256, 256>>>(src, dst);
    k_node <<<N_NODES / 4, 256>>>(eps, bias, out);   // 12500 blocks exact
}

// round 17
// speedup vs baseline: 1.6079x; 1.0522x over previous
#include <cuda_runtime.h>
#include <math_constants.h>

#define N_NODES 50000
#define N_EDGES 1600000
#define HEADS 8
#define OUT_FEAT 16
#define IN_FEAT 128
#define HF 128            // HEADS*OUT_FEAT
#define CAP 128           // per-node slot capacity (Poisson(32); P(>128) ~ 1e-35)
#define TILE_N 64         // nodes per proj block (2 per thread)
#define NB_PROJ ((N_NODES + TILE_N - 1) / TILE_N)   // 782
#define NB_EDGE ((N_EDGES + 255) / 256)             // 6250

// ---- scratch (device globals; no allocations allowed) ----
__device__ float4 g_h4[N_NODES * 32];      // h as float4 [N][H][4] = 25.6 MB
__device__ float4 g_post[N_NODES * HEADS]; // (loc_l, loc_r, exp(lsl), exp(lsr)), 6.4 MB
__device__ int2   g_es[(size_t)N_NODES * CAP]; // bucket: {src, edge_id}
__device__ int    g_cur[N_NODES];          // per-node slot cursor (zeroed at load; reset by k_node)

#define FMA2(acc, a, b) \
    asm("fma.rn.f32x2 %0, %1, %2, %0;" : "+l"(acc) : "l"(a), "l"(b))

// ---- fused projection + edge-slot kernel (independent work, one launch) ----
// blocks [0, NB_PROJ): proj path (R10-proven inner loop, untouched).
// blocks [NB_PROJ, NB_PROJ+NB_EDGE): edge slot assignment.
__global__ void k_projedge(const float* __restrict__ feat, const float* __restrict__ W_fc,
                           const float* __restrict__ W_post, const float* __restrict__ b_post,
                           const int* __restrict__ src, const int* __restrict__ dst) {
    __shared__ float sfT[IN_FEAT][TILE_N + 1];  // transposed feat tile
    __shared__ float sw[32][HF];                // weight K-chunk
    int t = threadIdx.x;

    if (blockIdx.x >= NB_PROJ) {
        // ---- edge path: slot assignment only ----
        int e = (blockIdx.x - NB_PROJ) * 256 + t;
        if (e < N_EDGES) {
            int d = dst[e];
            int c = atomicAdd(&g_cur[d], 1);
            if (c < CAP) g_es[(size_t)d * CAP + c] = make_int2(src[e], e);
        }
        return;
    }

    // ---- proj path ----
    int lane = t & 31;
    int hd = t >> 5;                            // warp id == head
    int n0 = blockIdx.x * TILE_N;
    int c0 = hd * 16;

    for (int i = t; i < TILE_N * IN_FEAT; i += 256) {
        int r = i >> 7, c = i & 127;
        int n = n0 + r;
        sfT[c][r] = (n < N_NODES) ? feat[(size_t)n * IN_FEAT + c] : 0.0f;
    }

    unsigned long long accA2[8], accB2[8];
#pragma unroll
    for (int j = 0; j < 8; ++j) { accA2[j] = 0ULL; accB2[j] = 0ULL; }

    for (int kc = 0; kc < IN_FEAT; kc += 32) {
        __syncthreads();
        for (int i = t; i < 32 * HF; i += 256) {
            int kk = i >> 7, c = i & 127;
            sw[kk][c] = W_fc[(size_t)(kc + kk) * HF + c];
        }
        __syncthreads();
#pragma unroll 4
        for (int kk = 0; kk < 32; ++kk) {
            float a0 = sfT[kc + kk][lane];
            float a1 = sfT[kc + kk][lane + 32];
            unsigned long long av0, av1;
            asm("mov.b64 %0, {%1, %1};" : "=l"(av0) : "f"(a0));
            asm("mov.b64 %0, {%1, %1};" : "=l"(av1) : "f"(a1));
            const unsigned long long* swp = (const unsigned long long*)&sw[kk][c0];
#pragma unroll
            for (int j = 0; j < 8; ++j) {
                unsigned long long bj = swp[j];      // broadcast LDS.64
                FMA2(accA2[j], av0, bj);
                FMA2(accB2[j], av1, bj);
            }
        }
    }

#pragma unroll
    for (int half = 0; half < 2; ++half) {
        int n = n0 + lane + half * 32;
        unsigned long long* acc2 = half ? accB2 : accA2;
        if (n < N_NODES) {
            float acc[16];
#pragma unroll
            for (int j = 0; j < 8; ++j)
                asm("mov.b64 {%0, %1}, %2;" : "=f"(acc[2 * j]), "=f"(acc[2 * j + 1]) : "l"(acc2[j]));
#pragma unroll
            for (int q = 0; q < 4; ++q)
                g_h4[n * 32 + hd * 4 + q] =
                    make_float4(acc[4 * q], acc[4 * q + 1], acc[4 * q + 2], acc[4 * q + 3]);
            float p0 = b_post[0], p1 = b_post[1], p2 = b_post[2], p3 = b_post[3];
#pragma unroll
            for (int j = 0; j < 16; ++j) {
                float hv = acc[j];
                p0 = fmaf(hv, W_post[j * 4 + 0], p0);
                p1 = fmaf(hv, W_post[j * 4 + 1], p1);
                p2 = fmaf(hv, W_post[j * 4 + 2], p2);
                p3 = fmaf(hv, W_post[j * 4 + 3], p3);
            }
            g_post[n * HEADS + hd] = make_float4(p0, p1, __expf(p2), __expf(p3));
        }
    }
}

// ---- per-node: WARP PAIR per node; phase B = 2 edges/iter, unroll x2 ----
// cnt is padded up to a multiple of 4 with zero slots -> no tail path.
__global__ void k_node(const float* __restrict__ eps,
                       const float* __restrict__ bias, float* __restrict__ out) {
    __shared__ float ssc[4][(CAP + 3) * 8];  // per-pair exp-scores (+pad slots)
    __shared__ int   ssn[4][CAP + 3];        // per-pair src ids (+pad slots)
    __shared__ float sdn[4][16];             // per-pair partial denoms
    int wl = threadIdx.x >> 5;
    int p  = wl >> 1;
    int wp = wl & 1;
    int nd = blockIdx.x * 4 + p;        // exact: 12500 * 4 = 50000
    int lane = threadIdx.x & 31;
    int cnt = min(g_cur[nd], CAP);
    const unsigned full = 0xFFFFFFFFu;
    const int2* bkt = g_es + (size_t)nd * CAP;
    float* sc = ssc[p];
    int*   sn = ssn[p];

    // ---- phase A: x = exp(score) for all 8 heads, pair-cooperative ----
    int head = lane & 7;
    int sgrp = (wp * 32 + lane) >> 3;
    float4 pd = g_post[nd * HEADS + head];
    float ds = 0.0f;
    for (int s = sgrp; s < cnt; s += 8) {
        int2 se = bkt[s];
        float4 ps = g_post[se.x * HEADS + head];
        float ep  = eps[(size_t)se.y * HEADS + head];
        float x = __expf(fmaf(ps.z * pd.w, ep, ps.x + pd.y));
        sc[s * 8 + head] = x;
        if (head == 0) sn[s] = se.x;
        ds += x;
    }
    ds += __shfl_xor_sync(full, ds, 8);
    ds += __shfl_xor_sync(full, ds, 16);
    if (lane < 8) sdn[p][wp * 8 + lane] = ds;
    // zero-pad 3 slots after cnt (covers unroll-4 padding; x=0 is a no-op edge)
    {
        int padi = wp * 32 + lane;      // 0..63 across pair
        int ps_  = padi >> 3;           // pad slot index 0..7 (use 0..2)
        int s = cnt + ps_;
        if (ps_ < 3 && s < CAP + 3) {
            sc[s * 8 + (padi & 7)] = 0.0f;
            if ((padi & 7) == 0) sn[s] = 0;
        }
    }
    __syncthreads();
    if (wp == 0 && lane == 0) g_cur[nd] = 0;   // reset cursor for next replay

    // ---- phase B: 4 edges per iteration over padded count (NO tail) ----
    int cntp = (cnt + 3) & ~3;          // multiple of 4; pads are zero slots
    int half16 = lane >> 4;             // which edge of each pair
    int l16    = lane & 15;             // float4 chunk within warp's 64 floats
    int head_b = wp * 4 + (l16 >> 2);   // head of this chunk
    int chunk  = wp * 16 + l16;         // float4 index within node's 32
    float4 acc = make_float4(0.f, 0.f, 0.f, 0.f);

    for (int s = 0; s < cntp; s += 4) {
        int   sa = sn[s + half16];
        int   sb = sn[s + 2 + half16];
        float xa = sc[(s + half16) * 8 + head_b];
        float xb = sc[(s + 2 + half16) * 8 + head_b];
        float4 va = g_h4[(size_t)sa * 32 + chunk];   // independent LDG.128 pair
        float4 vb = g_h4[(size_t)sb * 32 + chunk];
        acc.x = fmaf(va.x, xa, acc.x); acc.y = fmaf(va.y, xa, acc.y);
        acc.z = fmaf(va.z, xa, acc.z); acc.w = fmaf(va.w, xa, acc.w);
        acc.x = fmaf(vb.x, xb, acc.x); acc.y = fmaf(vb.y, xb, acc.y);
        acc.z = fmaf(vb.z, xb, acc.z); acc.w = fmaf(vb.w, xb, acc.w);
    }
    // combine the two edge-halves
    acc.x += __shfl_xor_sync(full, acc.x, 16);
    acc.y += __shfl_xor_sync(full, acc.y, 16);
    acc.z += __shfl_xor_sync(full, acc.z, 16);
    acc.w += __shfl_xor_sync(full, acc.w, 16);

    if (half16 == 0) {
        float dtot = sdn[p][head_b] + sdn[p][8 + head_b];
        float rd = (cnt > 0) ? 1.0f / dtot : 0.0f;
        float4 bv = ((const float4*)bias)[chunk];
        float4 o;
        o.x = fmaf(acc.x, rd, bv.x);
        o.y = fmaf(acc.y, rd, bv.y);
        o.z = fmaf(acc.z, rd, bv.z);
        o.w = fmaf(acc.w, rd, bv.w);
        ((float4*)out)[(size_t)nd * 32 + chunk] = o;
    }
}

extern "C" void kernel_launch(void* const* d_in, const int* in_sizes, int n_in,
                              void* d_out, int out_size) {
    const float* feat   = (const float*)d_in[0];
    const int*   src    = (const int*)  d_in[1];
    const int*   dst    = (const int*)  d_in[2];
    const float* eps    = (const float*)d_in[3];
    const float* W_fc   = (const float*)d_in[4];
    const float* W_post = (const float*)d_in[5];
    const float* b_post = (const float*)d_in[6];
    const float* bias   = (const float*)d_in[7];
    float* out = (float*)d_out;

    k_projedge <<<NB_PROJ + NB_EDGE, 256>>>(feat, W_fc, W_post, b_post, src, dst);
    k_node     <<<N_NODES / 4, 256>>>(eps, bias, out);   // 12500 blocks exact
}